// round 2
// baseline (speedup 1.0000x reference)
#include <cuda_runtime.h>
#include <cstdint>

// ---------------------------------------------------------------------------
// GCN restructured as CSR-gather (no per-edge global reductions):
//   p = (x @ W1) * dinv                       [N,32]   (gemm1)
//   CSR: edges grouped by dst                          (deg -> scan -> place)
//   gather1: q[n] = dinv*(dinv*(sum_{s in nbr(n)} p[s] + p[n]) + b1)
//   gather2: h[n] = dinv*(sum q[s] + q[n]);  red-add h into pool[batch[n]]
//   head:    pooled = pool/cnt; o2=pooled@W2+b2; z=relu(o2@fcW1+fcb1);
//            batchnorm; softplus(z@fcW2+fcb2)
// ---------------------------------------------------------------------------

#define MAXN 100000
#define MAXE 1600000
#define MAXG 256
#define C 32

__device__ int   g_src[MAXE];
__device__ int   g_dst[MAXE];
__device__ int   g_csr[MAXE];       // src ids grouped by dst
__device__ int   g_deg[MAXN];
__device__ int   g_off[MAXN];       // CSR row offsets (exclusive scan of deg)
__device__ int   g_cur[MAXN];       // running cursor for placement
__device__ float g_dinv[MAXN];
__device__ float g_p[MAXN * C];     // layer-1 pre-scaled features
__device__ float g_q[MAXN * C];     // layer-2 pre-scaled features
__device__ float g_pool[MAXG * C];  // per-graph sums (pre-mean, pre-W2)
__device__ int   g_flags[2];        // [0]=edge_index is int64, [1]=batch is int64

static inline int ceil_div(int a, int b) { return (a + b - 1) / b; }

// ---------------------------------------------------------------------------
// dtype detection (int64 vs int32): positive int64 -> all odd 32-bit words 0.
// ---------------------------------------------------------------------------
__global__ void k_detect(const unsigned* __restrict__ e, long ewords,
                         const unsigned* __restrict__ b, long bwords) {
    __shared__ unsigned se, sb;
    if (threadIdx.x == 0) { se = 0u; sb = 0u; }
    __syncthreads();
    unsigned a = 0u, c = 0u;
    long eh = ewords / 2, bh = bwords / 2;
    for (int s = 0; s < 16; s++) {
        long idx = (long)(threadIdx.x * 16 + s);
        long j = (idx * eh) / 4096;
        a |= e[2 * j + 1];
        long k = (idx * bh) / 4096;
        c |= b[2 * k + 1];
    }
    atomicOr(&se, a);
    atomicOr(&sb, c);
    __syncthreads();
    if (threadIdx.x == 0) {
        g_flags[0] = (se == 0u) ? 1 : 0;
        g_flags[1] = (sb == 0u) ? 1 : 0;
    }
}

__device__ __forceinline__ int idx_get(const void* p, long i, int is64) {
    return is64 ? (int)((const long long*)p)[i] : ((const int*)p)[i];
}

// ---------------------------------------------------------------------------
// Convert edge_index -> int32 arrays + degree count on dst
// ---------------------------------------------------------------------------
__global__ void k_deg(const void* __restrict__ eidx, int E) {
    int e = blockIdx.x * blockDim.x + threadIdx.x;
    if (e >= E) return;
    int is64 = g_flags[0];
    int s = idx_get(eidx, e, is64);
    int t = idx_get(eidx, (long)E + e, is64);
    g_src[e] = s;
    g_dst[e] = t;
    atomicAdd(&g_deg[t], 1);
}

// ---------------------------------------------------------------------------
// Single-block exclusive scan of deg -> off, cur; also dinv = rsqrt(1+deg).
// ---------------------------------------------------------------------------
__global__ void k_scan(int N) {
    __shared__ int sh[1024];
    int tid = threadIdx.x;
    int chunk = (N + 1023) / 1024;
    int start = tid * chunk;
    int end = min(start + chunk, N);

    int s = 0;
    for (int i = start; i < end; i++) s += g_deg[i];

    sh[tid] = s;
    __syncthreads();
    // Kogge-Stone inclusive scan
    for (int off = 1; off < 1024; off <<= 1) {
        int v = (tid >= off) ? sh[tid - off] : 0;
        __syncthreads();
        sh[tid] += v;
        __syncthreads();
    }
    int run = (tid > 0) ? sh[tid - 1] : 0;

    for (int i = start; i < end; i++) {
        int d = g_deg[i];
        g_off[i] = run;
        g_cur[i] = run;
        g_dinv[i] = rsqrtf(1.0f + (float)d);
        run += d;
    }
}

// ---------------------------------------------------------------------------
// CSR placement: csr[slot] = src, slots grouped by dst
// ---------------------------------------------------------------------------
__global__ void k_place(int E) {
    int e = blockIdx.x * blockDim.x + threadIdx.x;
    if (e >= E) return;
    int t = g_dst[e];
    int slot = atomicAdd(&g_cur[t], 1);
    g_csr[slot] = g_src[e];
}

// ---------------------------------------------------------------------------
// GEMM1: p[n,:] = dinv[n] * (x[n,:] @ W1).  2 nodes per thread for FMA ILP.
// ---------------------------------------------------------------------------
__global__ void __launch_bounds__(256) k_gemm1(const float* __restrict__ x,
                                               const float* __restrict__ W1, int N) {
    __shared__ float sW[128 * C];
    for (int i = threadIdx.x; i < 128 * C; i += blockDim.x) sW[i] = W1[i];
    __syncthreads();

    int n0 = (blockIdx.x * blockDim.x + threadIdx.x) * 2;
    if (n0 >= N) return;
    int n1 = (n0 + 1 < N) ? (n0 + 1) : n0;

    float acc0[C], acc1[C];
#pragma unroll
    for (int j = 0; j < C; j++) { acc0[j] = 0.0f; acc1[j] = 0.0f; }

    const float4* xr0 = (const float4*)(x + (size_t)n0 * 128);
    const float4* xr1 = (const float4*)(x + (size_t)n1 * 128);
#pragma unroll 2
    for (int k4 = 0; k4 < 32; k4++) {
        float4 xa = __ldg(&xr0[k4]);
        float4 xb = __ldg(&xr1[k4]);
        const float* fa = (const float*)&xa;
        const float* fb = (const float*)&xb;
#pragma unroll
        for (int kk = 0; kk < 4; kk++) {
            float va = fa[kk], vb = fb[kk];
            const float4* wr = (const float4*)(sW + (k4 * 4 + kk) * C);
#pragma unroll
            for (int j4 = 0; j4 < C / 4; j4++) {
                float4 w = wr[j4];
                acc0[j4 * 4 + 0] = fmaf(va, w.x, acc0[j4 * 4 + 0]);
                acc0[j4 * 4 + 1] = fmaf(va, w.y, acc0[j4 * 4 + 1]);
                acc0[j4 * 4 + 2] = fmaf(va, w.z, acc0[j4 * 4 + 2]);
                acc0[j4 * 4 + 3] = fmaf(va, w.w, acc0[j4 * 4 + 3]);
                acc1[j4 * 4 + 0] = fmaf(vb, w.x, acc1[j4 * 4 + 0]);
                acc1[j4 * 4 + 1] = fmaf(vb, w.y, acc1[j4 * 4 + 1]);
                acc1[j4 * 4 + 2] = fmaf(vb, w.z, acc1[j4 * 4 + 2]);
                acc1[j4 * 4 + 3] = fmaf(vb, w.w, acc1[j4 * 4 + 3]);
            }
        }
    }
    float d0 = g_dinv[n0];
    float d1 = g_dinv[n1];
    float4* o0 = (float4*)(g_p + (size_t)n0 * C);
    float4* o1 = (float4*)(g_p + (size_t)n1 * C);
#pragma unroll
    for (int j4 = 0; j4 < C / 4; j4++) {
        o0[j4] = make_float4(acc0[j4 * 4] * d0, acc0[j4 * 4 + 1] * d0,
                             acc0[j4 * 4 + 2] * d0, acc0[j4 * 4 + 3] * d0);
    }
    if (n1 != n0) {
#pragma unroll
        for (int j4 = 0; j4 < C / 4; j4++) {
            o1[j4] = make_float4(acc1[j4 * 4] * d1, acc1[j4 * 4 + 1] * d1,
                                 acc1[j4 * 4 + 2] * d1, acc1[j4 * 4 + 3] * d1);
        }
    }
}

// ---------------------------------------------------------------------------
// Gather layer 1: 8 threads per node, each owns one float4 column chunk.
//   q[n] = dinv*(dinv*(sum p[nbr] + p[n]) + b1)
// ---------------------------------------------------------------------------
__global__ void k_gather1(const float* __restrict__ b1, int N) {
    int node = blockIdx.x * 32 + (threadIdx.x >> 3);
    int lane = threadIdx.x & 7;
    if (node >= N) return;

    int beg = g_off[node];
    int end = beg + g_deg[node];

    const float4* P = (const float4*)g_p;
    float4 acc = __ldg(&P[(size_t)node * 8 + lane]);  // self-loop

    int e = beg;
    for (; e + 1 < end; e += 2) {
        int s0 = g_csr[e];
        int s1 = g_csr[e + 1];
        float4 v0 = __ldg(&P[(size_t)s0 * 8 + lane]);
        float4 v1 = __ldg(&P[(size_t)s1 * 8 + lane]);
        acc.x += v0.x; acc.y += v0.y; acc.z += v0.z; acc.w += v0.w;
        acc.x += v1.x; acc.y += v1.y; acc.z += v1.z; acc.w += v1.w;
    }
    if (e < end) {
        int s0 = g_csr[e];
        float4 v0 = __ldg(&P[(size_t)s0 * 8 + lane]);
        acc.x += v0.x; acc.y += v0.y; acc.z += v0.z; acc.w += v0.w;
    }

    float di = g_dinv[node];
    float4 b = ((const float4*)b1)[lane];
    float4 q;
    q.x = di * (di * acc.x + b.x);
    q.y = di * (di * acc.y + b.y);
    q.z = di * (di * acc.z + b.z);
    q.w = di * (di * acc.w + b.w);
    ((float4*)g_q)[(size_t)node * 8 + lane] = q;
}

// ---------------------------------------------------------------------------
// Gather layer 2 + fused pooling:
//   h[n] = dinv*(sum q[nbr] + q[n]);  pool[batch[n]] += h[n]
// ---------------------------------------------------------------------------
__device__ __forceinline__ void red_add_v4(float* ptr, float4 v) {
    asm volatile("red.global.add.v4.f32 [%0], {%1, %2, %3, %4};"
                 :: "l"(ptr), "f"(v.x), "f"(v.y), "f"(v.z), "f"(v.w)
                 : "memory");
}

__global__ void k_gather2(const void* __restrict__ batch, int N) {
    int node = blockIdx.x * 32 + (threadIdx.x >> 3);
    int lane = threadIdx.x & 7;
    if (node >= N) return;

    int beg = g_off[node];
    int end = beg + g_deg[node];

    const float4* Q = (const float4*)g_q;
    float4 acc = __ldg(&Q[(size_t)node * 8 + lane]);  // self-loop

    int e = beg;
    for (; e + 1 < end; e += 2) {
        int s0 = g_csr[e];
        int s1 = g_csr[e + 1];
        float4 v0 = __ldg(&Q[(size_t)s0 * 8 + lane]);
        float4 v1 = __ldg(&Q[(size_t)s1 * 8 + lane]);
        acc.x += v0.x; acc.y += v0.y; acc.z += v0.z; acc.w += v0.w;
        acc.x += v1.x; acc.y += v1.y; acc.z += v1.z; acc.w += v1.w;
    }
    if (e < end) {
        int s0 = g_csr[e];
        float4 v0 = __ldg(&Q[(size_t)s0 * 8 + lane]);
        acc.x += v0.x; acc.y += v0.y; acc.z += v0.z; acc.w += v0.w;
    }

    float di = g_dinv[node];
    float4 h = make_float4(di * acc.x, di * acc.y, di * acc.z, di * acc.w);
    int gidx = idx_get(batch, node, g_flags[1]);
    red_add_v4(g_pool + (size_t)gidx * C + lane * 4, h);
}

// ---------------------------------------------------------------------------
// Head (single block, one thread per graph): counts via binary search, mean,
// o2 = pooled@W2+b2; z = relu(o2@fcW1+fcb1); batchnorm; softplus(z@fcW2+fcb2)
// ---------------------------------------------------------------------------
__global__ void k_head(const void* __restrict__ batch, int N,
                       const float* __restrict__ W2, const float* __restrict__ b2,
                       const float* __restrict__ fcW1, const float* __restrict__ fcb1,
                       const float* __restrict__ gamma, const float* __restrict__ beta,
                       const float* __restrict__ fcW2, const float* __restrict__ fcb2,
                       float* __restrict__ out, int G) {
    __shared__ float sW2[32 * 64];
    __shared__ float sF1[64 * 32];
    __shared__ float sb2[64], sfb1[32], sgam[32], sbet[32], sfw2[32];
    __shared__ float ssum[32], ssq[32];
    __shared__ float sfb2;

    int tid = threadIdx.x;
    for (int i = tid; i < 32 * 64; i += blockDim.x) sW2[i] = W2[i];
    for (int i = tid; i < 64 * 32; i += blockDim.x) sF1[i] = fcW1[i];
    if (tid < 64) sb2[tid] = b2[tid];
    if (tid < 32) {
        sfb1[tid] = fcb1[tid]; sgam[tid] = gamma[tid]; sbet[tid] = beta[tid];
        sfw2[tid] = fcW2[tid]; ssum[tid] = 0.0f; ssq[tid] = 0.0f;
    }
    if (tid == 0) sfb2 = fcb2[0];
    __syncthreads();

    int g = tid;
    int is64 = g_flags[1];

    // node count of graph g via two binary searches in sorted batch
    int lo = 0, hi = N;
    while (lo < hi) { int m = (lo + hi) >> 1; if (idx_get(batch, m, is64) < g) lo = m + 1; else hi = m; }
    int start = lo;
    hi = N;
    while (lo < hi) { int m = (lo + hi) >> 1; if (idx_get(batch, m, is64) < g + 1) lo = m + 1; else hi = m; }
    int cnt = lo - start;
    float inv_cnt = 1.0f / (float)max(cnt, 1);

    float r[32];
#pragma unroll
    for (int i = 0; i < 32; i++) r[i] = g_pool[g * 32 + i] * inv_cnt;

    float o2[64];
#pragma unroll
    for (int j = 0; j < 64; j++) o2[j] = sb2[j];
    for (int k = 0; k < 32; k++) {
        float rk = r[k];
#pragma unroll
        for (int j = 0; j < 64; j++) o2[j] = fmaf(rk, sW2[k * 64 + j], o2[j]);
    }

    float z[32];
#pragma unroll
    for (int i = 0; i < 32; i++) z[i] = sfb1[i];
    for (int j = 0; j < 64; j++) {
        float oj = o2[j];
#pragma unroll
        for (int i = 0; i < 32; i++) z[i] = fmaf(oj, sF1[j * 32 + i], z[i]);
    }
#pragma unroll
    for (int i = 0; i < 32; i++) z[i] = fmaxf(z[i], 0.0f);

    for (int i = 0; i < 32; i++) {
        float v = z[i], v2 = v * v;
#pragma unroll
        for (int o = 16; o > 0; o >>= 1) {
            v += __shfl_down_sync(0xFFFFFFFFu, v, o);
            v2 += __shfl_down_sync(0xFFFFFFFFu, v2, o);
        }
        if ((tid & 31) == 0) { atomicAdd(&ssum[i], v); atomicAdd(&ssq[i], v2); }
    }
    __syncthreads();

    float acc = sfb2;
    float invG = 1.0f / (float)G;
#pragma unroll
    for (int i = 0; i < 32; i++) {
        float mu = ssum[i] * invG;
        float var = ssq[i] * invG - mu * mu;
        float zb = (z[i] - mu) * rsqrtf(var + 1e-5f) * sgam[i] + sbet[i];
        acc = fmaf(zb, sfw2[i], acc);
    }
    out[g] = fmaxf(acc, 0.0f) + log1pf(expf(-fabsf(acc)));
}

// ---------------------------------------------------------------------------
extern "C" void kernel_launch(void* const* d_in, const int* in_sizes, int n_in,
                              void* d_out, int out_size) {
    const float* x     = (const float*)d_in[0];
    const void*  eidx  = d_in[1];
    const void*  batch = d_in[2];
    const float* W1    = (const float*)d_in[3];
    const float* b1    = (const float*)d_in[4];
    const float* W2    = (const float*)d_in[5];
    const float* b2    = (const float*)d_in[6];
    const float* fcW1  = (const float*)d_in[7];
    const float* fcb1  = (const float*)d_in[8];
    const float* gamma = (const float*)d_in[9];
    const float* beta  = (const float*)d_in[10];
    const float* fcW2  = (const float*)d_in[11];
    const float* fcb2  = (const float*)d_in[12];

    int N = in_sizes[0] / 128;
    int E = in_sizes[1] / 2;
    int G = out_size;

    void *pdeg, *ppool;
    cudaGetSymbolAddress(&pdeg, g_deg);
    cudaGetSymbolAddress(&ppool, g_pool);

    cudaMemsetAsync(pdeg, 0, (size_t)N * sizeof(int));
    cudaMemsetAsync(ppool, 0, (size_t)G * C * sizeof(float));

    k_detect<<<1, 256>>>((const unsigned*)eidx, (long)2 * E,
                         (const unsigned*)batch, (long)N);
    k_deg<<<ceil_div(E, 256), 256>>>(eidx, E);
    k_scan<<<1, 1024>>>(N);
    k_place<<<ceil_div(E, 256), 256>>>(E);
    k_gemm1<<<ceil_div(N, 512), 256>>>(x, W1, N);
    k_gather1<<<ceil_div(N, 32), 256>>>(b1, N);
    k_gather2<<<ceil_div(N, 32), 256>>>(batch, N);
    k_head<<<1, G>>>(batch, N, W2, b2, fcW1, fcb1, gamma, beta, fcW2, fcb2,
                     (float*)d_out, G);
}

// round 3
// speedup vs baseline: 2.0953x; 2.0953x over previous
#include <cuda_runtime.h>
#include <cstdint>

// ---------------------------------------------------------------------------
// GCN via CSR-gather:
//   p = (x @ W1) * dinv
//   gather1: q[n] = dinv*(dinv*(sum_{s in nbr(n)} p[s] + p[n]) + b1)
//   gather2: h[n] = dinv*(sum q[s] + q[n]);  pool[batch[n]] += h  (red.v4)
//   head: mean, @W2+b2, relu(@fcW1+fcb1), batchnorm, softplus(@fcW2+fcb2)
// Launch order keeps k_gather1 in profiled slot 6.
// ---------------------------------------------------------------------------

#define MAXN 100000
#define MAXE 1600000
#define MAXG 256
#define C 32

__device__ int   g_csr[MAXE];       // src ids grouped by dst
__device__ int   g_deg[MAXN];
__device__ int   g_off[MAXN];       // CSR row offsets
__device__ int   g_cur[MAXN];       // placement cursors
__device__ float g_dinv[MAXN];
__device__ float g_p[MAXN * C];
__device__ float g_q[MAXN * C];
__device__ float g_pool[MAXG * C];
__device__ int   g_flags[2];        // [0]=edge_index int64, [1]=batch int64
__device__ int   g_part[256];       // scan block partials
__device__ int   g_done;            // scan arrival counter

static inline int ceil_div(int a, int b) { return (a + b - 1) / b; }

__device__ __forceinline__ int idx_get(const void* p, long i, int is64) {
    return is64 ? (int)((const long long*)p)[i] : ((const int*)p)[i];
}

// ---------------------------------------------------------------------------
// init: zero deg/pool/done everywhere; block 0 detects index dtypes
// (positive int64 => every odd 32-bit word is zero; sample 4096 odd words)
// ---------------------------------------------------------------------------
__global__ void k_init(const unsigned* __restrict__ e, long ewords,
                       const unsigned* __restrict__ b, long bwords,
                       int N, int G) {
    int stride = gridDim.x * blockDim.x;
    int t = blockIdx.x * blockDim.x + threadIdx.x;
    for (int i = t; i < N; i += stride) g_deg[i] = 0;
    for (int i = t; i < G * C; i += stride) g_pool[i] = 0.0f;
    if (t == 0) g_done = 0;

    if (blockIdx.x == 0) {
        __shared__ unsigned se, sb;
        if (threadIdx.x == 0) { se = 0u; sb = 0u; }
        __syncthreads();
        unsigned a = 0u, c = 0u;
        long eh = ewords / 2, bh = bwords / 2;
        for (int s = 0; s < 16; s++) {
            long idx = (long)(threadIdx.x * 16 + s);
            long j = (idx * eh) / 4096;
            a |= e[2 * j + 1];
            long k = (idx * bh) / 4096;
            c |= b[2 * k + 1];
        }
        atomicOr(&se, a);
        atomicOr(&sb, c);
        __syncthreads();
        if (threadIdx.x == 0) {
            g_flags[0] = (se == 0u) ? 1 : 0;
            g_flags[1] = (sb == 0u) ? 1 : 0;
        }
    }
}

// ---------------------------------------------------------------------------
// degree count on dst (reads edge_index directly)
// ---------------------------------------------------------------------------
__global__ void k_deg(const void* __restrict__ eidx, int E) {
    int is64 = g_flags[0];
    int stride = gridDim.x * blockDim.x;
    for (int ee = blockIdx.x * blockDim.x + threadIdx.x; ee < E; ee += stride) {
        int tgt = idx_get(eidx, (long)E + ee, is64);
        atomicAdd(&g_deg[tgt], 1);
    }
}

// ---------------------------------------------------------------------------
// One-kernel exclusive scan of deg -> off/cur, plus dinv.
// <=98 blocks x 1024 threads (1 elem/thread); all blocks co-resident, so a
// publish + spin on an arrival counter is safe.
// ---------------------------------------------------------------------------
__global__ void k_scan(int N) {
    __shared__ int warp_sums[32];
    __shared__ int block_prefix_sh;

    int t = threadIdx.x;
    int i = blockIdx.x * 1024 + t;
    int d = (i < N) ? g_deg[i] : 0;

    // warp inclusive scan
    int v = d;
#pragma unroll
    for (int o = 1; o < 32; o <<= 1) {
        int u = __shfl_up_sync(0xFFFFFFFFu, v, o);
        if ((t & 31) >= o) v += u;
    }
    if ((t & 31) == 31) warp_sums[t >> 5] = v;
    __syncthreads();
    if (t < 32) {
        int w = warp_sums[t];
#pragma unroll
        for (int o = 1; o < 32; o <<= 1) {
            int u = __shfl_up_sync(0xFFFFFFFFu, w, o);
            if (t >= o) w += u;
        }
        warp_sums[t] = w;
    }
    __syncthreads();
    int warp_base = (t >= 32) ? warp_sums[(t >> 5) - 1] : 0;
    int excl_local = warp_base + v - d;       // exclusive within block
    int block_total = warp_sums[31];

    // publish block total, wait for all, then sum predecessors
    if (t == 0) {
        g_part[blockIdx.x] = block_total;
        __threadfence();
        atomicAdd(&g_done, 1);
        while (atomicAdd(&g_done, 0) < (int)gridDim.x) { }
        int pre = 0;
        for (int bb = 0; bb < (int)blockIdx.x; bb++) pre += g_part[bb];
        block_prefix_sh = pre;
    }
    __syncthreads();
    int excl = block_prefix_sh + excl_local;

    if (i < N) {
        g_off[i] = excl;
        g_cur[i] = excl;
        g_dinv[i] = rsqrtf(1.0f + (float)d);
    }
}

// ---------------------------------------------------------------------------
// CSR placement
// ---------------------------------------------------------------------------
__global__ void k_place(const void* __restrict__ eidx, int E) {
    int is64 = g_flags[0];
    int stride = gridDim.x * blockDim.x;
    for (int ee = blockIdx.x * blockDim.x + threadIdx.x; ee < E; ee += stride) {
        int s = idx_get(eidx, ee, is64);
        int tgt = idx_get(eidx, (long)E + ee, is64);
        int slot = atomicAdd(&g_cur[tgt], 1);
        g_csr[slot] = s;
    }
}

// ---------------------------------------------------------------------------
// GEMM1 with packed fma.rn.f32x2: p[n,:] = dinv[n] * (x[n,:] @ W1)
// ---------------------------------------------------------------------------
__global__ void __launch_bounds__(256) k_gemm1(const float* __restrict__ x,
                                               const float* __restrict__ W1, int N) {
    __shared__ unsigned long long sW[128 * 16];   // W1 as f32x2 pairs
    const unsigned long long* Wp = (const unsigned long long*)W1;
    for (int i = threadIdx.x; i < 128 * 16; i += 256) sW[i] = Wp[i];
    __syncthreads();

    int n = blockIdx.x * 256 + threadIdx.x;
    if (n >= N) return;

    unsigned long long acc[16];
#pragma unroll
    for (int j = 0; j < 16; j++) acc[j] = 0ull;

    const float4* xr = (const float4*)(x + (size_t)n * 128);
#pragma unroll 2
    for (int k4 = 0; k4 < 32; k4++) {
        float4 xv = __ldg(&xr[k4]);
        const float* xf = (const float*)&xv;
#pragma unroll
        for (int kk = 0; kk < 4; kk++) {
            unsigned xb = __float_as_uint(xf[kk]);
            unsigned long long xx;
            asm("mov.b64 %0, {%1, %1};" : "=l"(xx) : "r"(xb));
            const unsigned long long* wr = sW + (k4 * 4 + kk) * 16;
#pragma unroll
            for (int j = 0; j < 16; j++) {
                asm("fma.rn.f32x2 %0, %1, %2, %0;"
                    : "+l"(acc[j]) : "l"(xx), "l"(wr[j]));
            }
        }
    }

    float di = g_dinv[n];
    float* out = g_p + (size_t)n * C;
#pragma unroll
    for (int j = 0; j < 16; j++) {
        unsigned lo, hi;
        asm("mov.b64 {%0, %1}, %2;" : "=r"(lo), "=r"(hi) : "l"(acc[j]));
        out[2 * j]     = __uint_as_float(lo) * di;
        out[2 * j + 1] = __uint_as_float(hi) * di;
    }
}

// ---------------------------------------------------------------------------
// Gather layer 1: 8 threads/node, float4 per lane, 4 independent chains.
// ---------------------------------------------------------------------------
__global__ void k_gather1(const float* __restrict__ b1, int N) {
    int node = blockIdx.x * 32 + (threadIdx.x >> 3);
    int lane = threadIdx.x & 7;
    if (node >= N) return;

    int beg = g_off[node];
    int end = beg + g_deg[node];

    const float4* P = (const float4*)g_p;
    float4 a0 = __ldg(&P[(size_t)node * 8 + lane]);  // self-loop
    float4 a1 = make_float4(0, 0, 0, 0);
    float4 a2 = make_float4(0, 0, 0, 0);
    float4 a3 = make_float4(0, 0, 0, 0);

    int e = beg;
    for (; e + 4 <= end; e += 4) {
        int i0 = g_csr[e], i1 = g_csr[e + 1], i2 = g_csr[e + 2], i3 = g_csr[e + 3];
        float4 v0 = __ldg(&P[(size_t)i0 * 8 + lane]);
        float4 v1 = __ldg(&P[(size_t)i1 * 8 + lane]);
        float4 v2 = __ldg(&P[(size_t)i2 * 8 + lane]);
        float4 v3 = __ldg(&P[(size_t)i3 * 8 + lane]);
        a0.x += v0.x; a0.y += v0.y; a0.z += v0.z; a0.w += v0.w;
        a1.x += v1.x; a1.y += v1.y; a1.z += v1.z; a1.w += v1.w;
        a2.x += v2.x; a2.y += v2.y; a2.z += v2.z; a2.w += v2.w;
        a3.x += v3.x; a3.y += v3.y; a3.z += v3.z; a3.w += v3.w;
    }
    for (; e < end; e++) {
        int i0 = g_csr[e];
        float4 v0 = __ldg(&P[(size_t)i0 * 8 + lane]);
        a0.x += v0.x; a0.y += v0.y; a0.z += v0.z; a0.w += v0.w;
    }
    a0.x += a1.x + a2.x + a3.x;
    a0.y += a1.y + a2.y + a3.y;
    a0.z += a1.z + a2.z + a3.z;
    a0.w += a1.w + a2.w + a3.w;

    float di = g_dinv[node];
    float4 b = ((const float4*)b1)[lane];
    float4 q;
    q.x = di * (di * a0.x + b.x);
    q.y = di * (di * a0.y + b.y);
    q.z = di * (di * a0.z + b.z);
    q.w = di * (di * a0.w + b.w);
    ((float4*)g_q)[(size_t)node * 8 + lane] = q;
}

// ---------------------------------------------------------------------------
// Gather layer 2 + fused pooling
// ---------------------------------------------------------------------------
__device__ __forceinline__ void red_add_v4(float* ptr, float4 v) {
    asm volatile("red.global.add.v4.f32 [%0], {%1, %2, %3, %4};"
                 :: "l"(ptr), "f"(v.x), "f"(v.y), "f"(v.z), "f"(v.w)
                 : "memory");
}

__global__ void k_gather2(const void* __restrict__ batch, int N) {
    int node = blockIdx.x * 32 + (threadIdx.x >> 3);
    int lane = threadIdx.x & 7;
    if (node >= N) return;

    int beg = g_off[node];
    int end = beg + g_deg[node];

    const float4* Q = (const float4*)g_q;
    float4 a0 = __ldg(&Q[(size_t)node * 8 + lane]);  // self-loop
    float4 a1 = make_float4(0, 0, 0, 0);
    float4 a2 = make_float4(0, 0, 0, 0);
    float4 a3 = make_float4(0, 0, 0, 0);

    int e = beg;
    for (; e + 4 <= end; e += 4) {
        int i0 = g_csr[e], i1 = g_csr[e + 1], i2 = g_csr[e + 2], i3 = g_csr[e + 3];
        float4 v0 = __ldg(&Q[(size_t)i0 * 8 + lane]);
        float4 v1 = __ldg(&Q[(size_t)i1 * 8 + lane]);
        float4 v2 = __ldg(&Q[(size_t)i2 * 8 + lane]);
        float4 v3 = __ldg(&Q[(size_t)i3 * 8 + lane]);
        a0.x += v0.x; a0.y += v0.y; a0.z += v0.z; a0.w += v0.w;
        a1.x += v1.x; a1.y += v1.y; a1.z += v1.z; a1.w += v1.w;
        a2.x += v2.x; a2.y += v2.y; a2.z += v2.z; a2.w += v2.w;
        a3.x += v3.x; a3.y += v3.y; a3.z += v3.z; a3.w += v3.w;
    }
    for (; e < end; e++) {
        int i0 = g_csr[e];
        float4 v0 = __ldg(&Q[(size_t)i0 * 8 + lane]);
        a0.x += v0.x; a0.y += v0.y; a0.z += v0.z; a0.w += v0.w;
    }
    a0.x += a1.x + a2.x + a3.x;
    a0.y += a1.y + a2.y + a3.y;
    a0.z += a1.z + a2.z + a3.z;
    a0.w += a1.w + a2.w + a3.w;

    float di = g_dinv[node];
    float4 h = make_float4(di * a0.x, di * a0.y, di * a0.z, di * a0.w);
    int gidx = idx_get(batch, node, g_flags[1]);
    red_add_v4(g_pool + (size_t)gidx * C + lane * 4, h);
}

// ---------------------------------------------------------------------------
// Head (1 block, 1 thread/graph)
// ---------------------------------------------------------------------------
__global__ void k_head(const void* __restrict__ batch, int N,
                       const float* __restrict__ W2, const float* __restrict__ b2,
                       const float* __restrict__ fcW1, const float* __restrict__ fcb1,
                       const float* __restrict__ gamma, const float* __restrict__ beta,
                       const float* __restrict__ fcW2, const float* __restrict__ fcb2,
                       float* __restrict__ out, int G) {
    __shared__ float sW2[32 * 64];
    __shared__ float sF1[64 * 32];
    __shared__ float sb2[64], sfb1[32], sgam[32], sbet[32], sfw2[32];
    __shared__ float ssum[32], ssq[32];
    __shared__ float sfb2;

    int tid = threadIdx.x;
    for (int i = tid; i < 32 * 64; i += blockDim.x) sW2[i] = W2[i];
    for (int i = tid; i < 64 * 32; i += blockDim.x) sF1[i] = fcW1[i];
    if (tid < 64) sb2[tid] = b2[tid];
    if (tid < 32) {
        sfb1[tid] = fcb1[tid]; sgam[tid] = gamma[tid]; sbet[tid] = beta[tid];
        sfw2[tid] = fcW2[tid]; ssum[tid] = 0.0f; ssq[tid] = 0.0f;
    }
    if (tid == 0) sfb2 = fcb2[0];
    __syncthreads();

    int g = tid;
    int is64 = g_flags[1];

    int lo = 0, hi = N;
    while (lo < hi) { int m = (lo + hi) >> 1; if (idx_get(batch, m, is64) < g) lo = m + 1; else hi = m; }
    int start = lo;
    hi = N;
    while (lo < hi) { int m = (lo + hi) >> 1; if (idx_get(batch, m, is64) < g + 1) lo = m + 1; else hi = m; }
    int cnt = lo - start;
    float inv_cnt = 1.0f / (float)max(cnt, 1);

    float r[32];
#pragma unroll
    for (int i = 0; i < 32; i++) r[i] = g_pool[g * 32 + i] * inv_cnt;

    float o2[64];
#pragma unroll
    for (int j = 0; j < 64; j++) o2[j] = sb2[j];
    for (int k = 0; k < 32; k++) {
        float rk = r[k];
#pragma unroll
        for (int j = 0; j < 64; j++) o2[j] = fmaf(rk, sW2[k * 64 + j], o2[j]);
    }

    float z[32];
#pragma unroll
    for (int i = 0; i < 32; i++) z[i] = sfb1[i];
    for (int j = 0; j < 64; j++) {
        float oj = o2[j];
#pragma unroll
        for (int i = 0; i < 32; i++) z[i] = fmaf(oj, sF1[j * 32 + i], z[i]);
    }
#pragma unroll
    for (int i = 0; i < 32; i++) z[i] = fmaxf(z[i], 0.0f);

    for (int i = 0; i < 32; i++) {
        float v = z[i], v2 = v * v;
#pragma unroll
        for (int o = 16; o > 0; o >>= 1) {
            v += __shfl_down_sync(0xFFFFFFFFu, v, o);
            v2 += __shfl_down_sync(0xFFFFFFFFu, v2, o);
        }
        if ((tid & 31) == 0) { atomicAdd(&ssum[i], v); atomicAdd(&ssq[i], v2); }
    }
    __syncthreads();

    float acc = sfb2;
    float invG = 1.0f / (float)G;
#pragma unroll
    for (int i = 0; i < 32; i++) {
        float mu = ssum[i] * invG;
        float var = ssq[i] * invG - mu * mu;
        float zb = (z[i] - mu) * rsqrtf(var + 1e-5f) * sgam[i] + sbet[i];
        acc = fmaf(zb, sfw2[i], acc);
    }
    out[g] = fmaxf(acc, 0.0f) + log1pf(expf(-fabsf(acc)));
}

// ---------------------------------------------------------------------------
extern "C" void kernel_launch(void* const* d_in, const int* in_sizes, int n_in,
                              void* d_out, int out_size) {
    const float* x     = (const float*)d_in[0];
    const void*  eidx  = d_in[1];
    const void*  batch = d_in[2];
    const float* W1    = (const float*)d_in[3];
    const float* b1    = (const float*)d_in[4];
    const float* W2    = (const float*)d_in[5];
    const float* b2    = (const float*)d_in[6];
    const float* fcW1  = (const float*)d_in[7];
    const float* fcb1  = (const float*)d_in[8];
    const float* gamma = (const float*)d_in[9];
    const float* beta  = (const float*)d_in[10];
    const float* fcW2  = (const float*)d_in[11];
    const float* fcb2  = (const float*)d_in[12];

    int N = in_sizes[0] / 128;
    int E = in_sizes[1] / 2;
    int G = out_size;

    // 1
    k_init<<<128, 256>>>((const unsigned*)eidx, (long)2 * E,
                         (const unsigned*)batch, (long)N, N, G);
    // 2
    k_deg<<<ceil_div(E, 512), 256>>>(eidx, E);
    // 3
    k_scan<<<ceil_div(N, 1024), 1024>>>(N);
    // 4
    k_place<<<ceil_div(E, 512), 256>>>(eidx, E);
    // 5
    k_gemm1<<<ceil_div(N, 256), 256>>>(x, W1, N);
    // 6  <-- profiled launch
    k_gather1<<<ceil_div(N, 32), 256>>>(b1, N);
    // 7
    k_gather2<<<ceil_div(N, 32), 256>>>(batch, N);
    // 8
    k_head<<<1, G>>>(batch, N, W2, b2, fcW1, fcb1, gamma, beta, fcW2, fcb2,
                     (float*)d_out, G);
}